// round 16
// baseline (speedup 1.0000x reference)
#include <cuda_runtime.h>
#include <cuda_bf16.h>
#include <math.h>
#include <cstdint>

// Problem dims (fixed by reference)
#define T_SEQ   1536
#define D_MODEL 2880
#define NH      64
#define NKV     8
#define HD      64
#define QKV_DIM 5120          // 64*(64+16)
#define QDIM    4096          // NH*HD
#define WIN     128
#define SM_SCALE 0.125f

// Scratch (allocation-free rule: device globals)
__device__ float g_qkv[T_SEQ * QKV_DIM];            // fp32 qkv (GEMM1 out)
__device__ float g_invf[32];                        // rope inv_freq table
// split-bf16 operands
__device__ __nv_bfloat16 g_xh[T_SEQ * D_MODEL];
__device__ __nv_bfloat16 g_xl[T_SEQ * D_MODEL];
__device__ __nv_bfloat16 g_wqh[D_MODEL * QKV_DIM];
__device__ __nv_bfloat16 g_wql[D_MODEL * QKV_DIM];
__device__ __nv_bfloat16 g_woh[QDIM * D_MODEL];
__device__ __nv_bfloat16 g_wol[QDIM * D_MODEL];
__device__ __nv_bfloat16 g_ath[T_SEQ * QDIM];       // attn out hi
__device__ __nv_bfloat16 g_atl[T_SEQ * QDIM];       // attn out lo
__device__ __nv_bfloat16 g_qh[T_SEQ * QKV_DIM];     // roped/scaled qkv hi
__device__ __nv_bfloat16 g_ql[T_SEQ * QKV_DIM];     // roped/scaled qkv lo

// ===========================================================================
// PTX helpers
// ===========================================================================
__device__ __forceinline__ uint32_t smem_u32(const void* p) {
    uint32_t a;
    asm("{ .reg .u64 t; cvta.to.shared.u64 t, %1; cvt.u32.u64 %0, t; }"
        : "=r"(a) : "l"(p));
    return a;
}
__device__ __forceinline__ void ldsm_x4(uint32_t r[4], uint32_t a) {
    asm volatile("ldmatrix.sync.aligned.m8n8.x4.shared.b16 {%0,%1,%2,%3}, [%4];"
        : "=r"(r[0]), "=r"(r[1]), "=r"(r[2]), "=r"(r[3]) : "r"(a));
}
__device__ __forceinline__ void ldsm_x4t(uint32_t r[4], uint32_t a) {
    asm volatile("ldmatrix.sync.aligned.m8n8.x4.trans.shared.b16 {%0,%1,%2,%3}, [%4];"
        : "=r"(r[0]), "=r"(r[1]), "=r"(r[2]), "=r"(r[3]) : "r"(a));
}
__device__ __forceinline__ void ldsm_x2(uint32_t r[2], uint32_t a) {
    asm volatile("ldmatrix.sync.aligned.m8n8.x2.shared.b16 {%0,%1}, [%2];"
        : "=r"(r[0]), "=r"(r[1]) : "r"(a));
}
__device__ __forceinline__ void mma16816(float c[4], const uint32_t a[4],
                                         const uint32_t b[2]) {
    asm volatile(
        "mma.sync.aligned.m16n8k16.row.col.f32.bf16.bf16.f32 "
        "{%0,%1,%2,%3}, {%4,%5,%6,%7}, {%8,%9}, {%0,%1,%2,%3};"
        : "+f"(c[0]), "+f"(c[1]), "+f"(c[2]), "+f"(c[3])
        : "r"(a[0]), "r"(a[1]), "r"(a[2]), "r"(a[3]), "r"(b[0]), "r"(b[1]));
}
__device__ __forceinline__ void cp16(uint32_t saddr, const void* gaddr,
                                     uint32_t srcsize) {
    asm volatile("cp.async.ca.shared.global [%0], [%1], 16, %2;"
        :: "r"(saddr), "l"(gaddr), "r"(srcsize));
}
__device__ __forceinline__ void cp_commit() {
    asm volatile("cp.async.commit_group;" ::: "memory");
}
template <int N>
__device__ __forceinline__ void cp_wait() {
    asm volatile("cp.async.wait_group %0;" :: "n"(N) : "memory");
}
// split fp32 pair into (hi, lo) packed bf16x2
__device__ __forceinline__ void split_pair(float x, float y,
                                           uint32_t& hi, uint32_t& lo) {
    __nv_bfloat16 hx = __float2bfloat16(x);
    __nv_bfloat16 hy = __float2bfloat16(y);
    float rx = x - __bfloat162float(hx);
    float ry = y - __bfloat162float(hy);
    __nv_bfloat162 hp = __halves2bfloat162(hx, hy);
    __nv_bfloat162 lp = __floats2bfloat162_rn(rx, ry);
    hi = *reinterpret_cast<uint32_t*>(&hp);
    lo = *reinterpret_cast<uint32_t*>(&lp);
}

// ===========================================================================
// Split kernel: fp32 -> (hi, lo) bf16, vectorized.
// ===========================================================================
__global__ void __launch_bounds__(256) split_kernel(
    const float4* __restrict__ in, uint2* __restrict__ hi,
    uint2* __restrict__ lo, int n4)
{
    int i = blockIdx.x * 256 + threadIdx.x;
    if (i < n4) {
        float4 v = in[i];
        uint32_t h0, l0, h1, l1;
        split_pair(v.x, v.y, h0, l0);
        split_pair(v.z, v.w, h1, l1);
        hi[i] = make_uint2(h0, h1);
        lo[i] = make_uint2(l0, l1);
    }
}

// ===========================================================================
// Split-bf16 HMMA GEMM with bias (pre-split operands).
// 3-stage cp.async pipeline, ONE barrier per chunk, 2 CTAs/SM.
// ===========================================================================
#define SA_HI_OFF 0
#define SA_LO_OFF 10240
#define SB_HI_OFF 20480
#define SB_LO_OFF 29184
#define BUF_STRIDE 37888
#define EP_PITCH  132
#define GEMM_SMEM_BYTES (3 * BUF_STRIDE)   // 113664; 2 CTAs/SM = 227328 <= 228KB

__global__ void __launch_bounds__(256, 2) hmma_gemm_bias(
    const __nv_bfloat16* __restrict__ Ah, const __nv_bfloat16* __restrict__ Al,
    const __nv_bfloat16* __restrict__ Bh, const __nv_bfloat16* __restrict__ Bl,
    const float* __restrict__ bias, float* __restrict__ C,
    int M, int N, int K)
{
    extern __shared__ char smem[];
    const uint32_t sb = smem_u32(smem);
    const int tid = threadIdx.x, lane = tid & 31, wid = tid >> 5;
    const int wm = wid >> 2, wn = wid & 3;
    const int m0 = blockIdx.y * 128, n0 = blockIdx.x * 128;

    float acc[4][4][4];
    #pragma unroll
    for (int mi = 0; mi < 4; mi++)
        #pragma unroll
        for (int ni = 0; ni < 4; ni++)
            #pragma unroll
            for (int q = 0; q < 4; q++) acc[mi][ni][q] = 0.f;

    const int am  = tid >> 2;
    const int aks = (tid & 3);
    const int bk  = tid >> 4;
    const int bns = (tid & 15);

    auto issue_chunk = [&](int k0, int buf) {
        const uint32_t bb = sb + (uint32_t)buf * BUF_STRIDE;
        #pragma unroll
        for (int r = 0; r < 2; r++) {
            int m = am + r * 64;
            const __nv_bfloat16* ga = Ah + (size_t)(m0 + m) * K + k0 + aks * 8;
            const __nv_bfloat16* gl = Al + (size_t)(m0 + m) * K + k0 + aks * 8;
            uint32_t so = (uint32_t)m * 80u + (uint32_t)aks * 16u;
            cp16(bb + SA_HI_OFF + so, ga, 16);
            cp16(bb + SA_LO_OFF + so, gl, 16);
        }
        #pragma unroll
        for (int r = 0; r < 2; r++) {
            int k = bk + r * 16;
            int ncol = n0 + bns * 8;
            uint32_t sz = (ncol < N) ? 16u : 0u;
            const __nv_bfloat16* gb = Bh + (size_t)(k0 + k) * N + ncol;
            const __nv_bfloat16* gl = Bl + (size_t)(k0 + k) * N + ncol;
            uint32_t so = (uint32_t)k * 272u + (uint32_t)bns * 16u;
            cp16(bb + SB_HI_OFF + so, gb, sz);
            cp16(bb + SB_LO_OFF + so, gl, sz);
        }
        cp_commit();
    };

    const int nch = K >> 5;
    issue_chunk(0, 0);
    if (nch > 1) issue_chunk(32, 1); else cp_commit();

    for (int ch = 0; ch < nch; ch++) {
        cp_wait<1>();            // chunk ch has landed (ch+1 may still fly)
        __syncthreads();         // single barrier per chunk

        // prefetch chunk ch+2 into buffer (ch+2)%3 — that buffer was last
        // read at chunk ch-1, finished by all warps before this barrier.
        if (ch + 2 < nch) issue_chunk((ch + 2) * 32, (ch + 2) % 3);
        else cp_commit();        // keep group count consistent for cp_wait<1>

        const uint32_t bufb = sb + (uint32_t)(ch % 3) * BUF_STRIDE;
        #pragma unroll
        for (int s = 0; s < 2; s++) {
            uint32_t ah[4][4], al[4][4], bh[4][2], bl[4][2];
            const uint32_t arow  = (uint32_t)(lane & 15);
            const uint32_t acolb = (uint32_t)(s * 32 + (lane >> 4) * 16);
            #pragma unroll
            for (int mi = 0; mi < 4; mi++) {
                uint32_t addr = bufb + SA_HI_OFF
                              + (uint32_t)(wm * 64 + mi * 16 + arow) * 80u + acolb;
                ldsm_x4(ah[mi], addr);
                ldsm_x4(al[mi], addr + (SA_LO_OFF - SA_HI_OFF));
            }
            const uint32_t brow = (uint32_t)(s * 16 + (lane & 15));
            #pragma unroll
            for (int pr = 0; pr < 2; pr++) {
                uint32_t bt[4], btl[4];
                uint32_t addr = bufb + SB_HI_OFF + brow * 272u
                              + (uint32_t)(wn * 32 + pr * 16
                                           + ((lane >> 4) & 1) * 8) * 2u;
                ldsm_x4t(bt, addr);
                ldsm_x4t(btl, addr + (SB_LO_OFF - SB_HI_OFF));
                bh[pr * 2][0]     = bt[0];  bh[pr * 2][1]     = bt[1];
                bh[pr * 2 + 1][0] = bt[2];  bh[pr * 2 + 1][1] = bt[3];
                bl[pr * 2][0]     = btl[0]; bl[pr * 2][1]     = btl[1];
                bl[pr * 2 + 1][0] = btl[2]; bl[pr * 2 + 1][1] = btl[3];
            }
            #pragma unroll
            for (int mi = 0; mi < 4; mi++)
                #pragma unroll
                for (int ni = 0; ni < 4; ni++) {
                    mma16816(acc[mi][ni], ah[mi], bh[ni]);
                    mma16816(acc[mi][ni], al[mi], bh[ni]);
                    mma16816(acc[mi][ni], ah[mi], bl[ni]);
                }
        }
    }
    __syncthreads();

    float* ep = (float*)smem;
    #pragma unroll
    for (int mi = 0; mi < 4; mi++) {
        int r0 = wm * 64 + mi * 16 + (lane >> 2);
        #pragma unroll
        for (int ni = 0; ni < 4; ni++) {
            int c = wn * 32 + ni * 8 + (lane & 3) * 2;
            ep[r0 * EP_PITCH + c]           = acc[mi][ni][0];
            ep[r0 * EP_PITCH + c + 1]       = acc[mi][ni][1];
            ep[(r0 + 8) * EP_PITCH + c]     = acc[mi][ni][2];
            ep[(r0 + 8) * EP_PITCH + c + 1] = acc[mi][ni][3];
        }
    }
    __syncthreads();
    for (int i = tid; i < 4096; i += 256) {
        int r = i >> 5, cq = (i & 31) * 4;
        int col = n0 + cq;
        if (col < N) {
            float4 b4 = *(const float4*)(bias + col);
            float4 o;
            o.x = ep[r * EP_PITCH + cq + 0] + b4.x;
            o.y = ep[r * EP_PITCH + cq + 1] + b4.y;
            o.z = ep[r * EP_PITCH + cq + 2] + b4.z;
            o.w = ep[r * EP_PITCH + cq + 3] + b4.w;
            *(float4*)(C + (size_t)(m0 + r) * N + col) = o;
        }
    }
}

// ---------------------------------------------------------------------------
// RoPE inv_freq table init (32 threads, double precision, once per launch)
// ---------------------------------------------------------------------------
__global__ void rope_table_kernel(float* __restrict__ invf_out)
{
    const int i = threadIdx.x;   // 0..31
    const double lgbase = log(150000.0);
    const double low  = 32.0 * log(1024.0 / (32.0 * 2.0 * M_PI)) / lgbase;
    const double high = 32.0 * log(1024.0 / ( 1.0 * 2.0 * M_PI)) / lgbase;
    double freq = pow(150000.0, (double)(2 * i) / 64.0);
    double ramp = ((double)i - low) / (high - low);
    ramp = fmin(1.0, fmax(0.0, ramp));
    double invf = ramp / (32.0 * freq) + (1.0 - ramp) / freq;
    invf_out[i] = (float)invf;
}

// ===========================================================================
// Fused RoPE + scale + split (one block per token, 256 threads)
// ===========================================================================
__global__ void __launch_bounds__(256) rope_split_qkv(
    const float* __restrict__ qkv, const float* __restrict__ invf,
    __nv_bfloat16* __restrict__ qh, __nv_bfloat16* __restrict__ ql)
{
    __shared__ float sinv[32];
    const int t = blockIdx.x;
    const int tid = threadIdx.x;
    if (tid < 32) sinv[tid] = invf[tid];
    __syncthreads();

    const float conc = 0.1f * logf(32.0f) + 1.0f;
    const float* row = qkv + (size_t)t * QKV_DIM;
    uint2* oh = (uint2*)(qh + (size_t)t * QKV_DIM);
    uint2* ol = (uint2*)(ql + (size_t)t * QKV_DIM);

    for (int i = tid; i < (NH + NKV) * 8; i += 256) {
        int hh = i >> 3, c = i & 7;
        int base = (hh < NH) ? hh * HD : QDIM + (hh - NH) * HD;
        const float4 a = ((const float4*)(row + base))[c];
        const float4 b = ((const float4*)(row + base))[c + 8];
        float na[4], nb[4];
        const float av[4] = {a.x, a.y, a.z, a.w};
        const float bv[4] = {b.x, b.y, b.z, b.w};
        #pragma unroll
        for (int q = 0; q < 4; q++) {
            float ang = (float)t * sinv[c * 4 + q];
            float s, cc;
            sincosf(ang, &s, &cc);
            cc *= conc; s *= conc;
            na[q] = av[q] * cc - bv[q] * s;
            nb[q] = bv[q] * cc + av[q] * s;
        }
        if (hh < NH) {
            #pragma unroll
            for (int q = 0; q < 4; q++) { na[q] *= SM_SCALE; nb[q] *= SM_SCALE; }
        }
        uint32_t h0, l0, h1, l1;
        split_pair(na[0], na[1], h0, l0);
        split_pair(na[2], na[3], h1, l1);
        oh[base / 4 + c] = make_uint2(h0, h1);
        ol[base / 4 + c] = make_uint2(l0, l1);
        split_pair(nb[0], nb[1], h0, l0);
        split_pair(nb[2], nb[3], h1, l1);
        oh[base / 4 + c + 8] = make_uint2(h0, h1);
        ol[base / 4 + c + 8] = make_uint2(l0, l1);
    }
    const int vbase4 = (QDIM + NKV * HD) / 4;
    for (int i = tid; i < 128; i += 256) {
        float4 v = ((const float4*)row)[vbase4 + i];
        uint32_t h0, l0, h1, l1;
        split_pair(v.x, v.y, h0, l0);
        split_pair(v.z, v.w, h1, l1);
        oh[vbase4 + i] = make_uint2(h0, h1);
        ol[vbase4 + i] = make_uint2(l0, l1);
    }
}

// ===========================================================================
// 8-token tiled MMA attention: block = (8 tokens, kv head), 256 threads.
// ===========================================================================
#define TQ   8
#define JT   144
#define BK_H 0
#define BK_L 20736
#define BV_H 41472
#define BV_L 62208
#define BQ_H 82944
#define BQ_L 92160
#define BP_H 101376
#define BP_L 120832
#define BO_F BQ_H                    // fp32 [64 q][68 d] aliases Q (17408<=18432)
#define ATTN_SMEM 140288

__global__ void __launch_bounds__(256) attn_kernel(
    const __nv_bfloat16* __restrict__ qh, const __nv_bfloat16* __restrict__ ql,
    const float* __restrict__ sinks,
    __nv_bfloat16* __restrict__ outh, __nv_bfloat16* __restrict__ outl)
{
    extern __shared__ char smc[];
    const uint32_t sb = smem_u32(smc);
    const int t0  = blockIdx.x * TQ;
    const int hkv = blockIdx.y;
    const int j0  = max(0, t0 - (WIN - 1));
    const int cntrows = t0 + TQ - j0;          // <= 135
    const int tid = threadIdx.x;
    const int warp = tid >> 5;
    const int lane = tid & 31;

    for (int i = tid; i < JT * 8; i += 256) {
        int jj = i >> 3, c8 = i & 7;
        int jc = min(jj, cntrows - 1);
        uint32_t sz = (jj < cntrows) ? 16u : 0u;
        size_t srck = (size_t)(j0 + jc) * QKV_DIM + QDIM + hkv * HD + c8 * 8;
        size_t srcv = srck + NKV * HD;
        uint32_t off = (uint32_t)jj * 144u + (uint32_t)c8 * 16u;
        cp16(sb + BK_H + off, qh + srck, sz);
        cp16(sb + BK_L + off, ql + srck, sz);
        cp16(sb + BV_H + off, qh + srcv, sz);
        cp16(sb + BV_L + off, ql + srcv, sz);
    }
    for (int i = tid; i < 1024; i += 256) {
        int hilo = i >> 9, row = (i >> 3) & 63, c8 = i & 7;
        int tt = t0 + (row >> 3), head = row & 7;
        size_t src = (size_t)tt * QKV_DIM + (hkv * 8 + head) * HD + c8 * 8;
        uint32_t off = (uint32_t)row * 144u + (uint32_t)c8 * 16u;
        if (hilo == 0) cp16(sb + BQ_H + off, qh + src, 16);
        else           cp16(sb + BQ_L + off, ql + src, 16);
    }
    cp_commit();
    cp_wait<0>();
    __syncthreads();

    const int tw  = t0 + warp;
    const int jlo = max(0, tw - (WIN - 1) - j0);
    const int jhi = tw - j0;

    float sc[9][4];
    {
        uint32_t bh[4][2], bl[4][2];
        #pragma unroll
        for (int ks = 0; ks < 4; ks++) {
            uint32_t addr = sb + BQ_H
                          + (uint32_t)(warp * 8 + (lane & 7)) * 144u
                          + (uint32_t)ks * 32u + (uint32_t)((lane >> 3) & 1) * 16u;
            ldsm_x2(bh[ks], addr);
            ldsm_x2(bl[ks], addr + (BQ_L - BQ_H));
        }
        #pragma unroll
        for (int mt = 0; mt < 9; mt++) {
            float c[4] = {0.f, 0.f, 0.f, 0.f};
            #pragma unroll
            for (int ks = 0; ks < 4; ks++) {
                uint32_t ah[4], al[4];
                uint32_t addr = sb + BK_H
                              + (uint32_t)(mt * 16 + (lane & 15)) * 144u
                              + (uint32_t)ks * 32u + (uint32_t)(lane >> 4) * 16u;
                ldsm_x4(ah, addr);
                ldsm_x4(al, addr + (BK_L - BK_H));
                mma16816(c, ah, bh[ks]);
                mma16816(c, al, bh[ks]);
                mma16816(c, ah, bl[ks]);
            }
            sc[mt][0] = c[0]; sc[mt][1] = c[1]; sc[mt][2] = c[2]; sc[mt][3] = c[3];
        }
    }

    {
        const int jb = lane >> 2;
        float m0 = -INFINITY, m1 = -INFINITY;
        #pragma unroll
        for (int mt = 0; mt < 9; mt++) {
            #pragma unroll
            for (int k = 0; k < 4; k++) {
                int jj = mt * 16 + jb + (k >> 1) * 8;
                if (jj < jlo || jj > jhi) sc[mt][k] = -INFINITY;
                if (k & 1) m1 = fmaxf(m1, sc[mt][k]);
                else       m0 = fmaxf(m0, sc[mt][k]);
            }
        }
        #pragma unroll
        for (int o = 4; o <= 16; o <<= 1) {
            m0 = fmaxf(m0, __shfl_xor_sync(~0u, m0, o));
            m1 = fmaxf(m1, __shfl_xor_sync(~0u, m1, o));
        }
        float s0 = 0.f, s1 = 0.f;
        #pragma unroll
        for (int mt = 0; mt < 9; mt++) {
            #pragma unroll
            for (int k = 0; k < 4; k++) {
                float m = (k & 1) ? m1 : m0;
                float e = (sc[mt][k] == -INFINITY) ? 0.f : expf(sc[mt][k] - m);
                sc[mt][k] = e;
                if (k & 1) s1 += e; else s0 += e;
            }
        }
        #pragma unroll
        for (int o = 4; o <= 16; o <<= 1) {
            s0 += __shfl_xor_sync(~0u, s0, o);
            s1 += __shfl_xor_sync(~0u, s1, o);
        }
        const int h0 = 2 * (lane & 3), h1 = h0 + 1;
        const float i0 = 1.f / (s0 + expf(sinks[hkv * 8 + h0] - m0));
        const float i1 = 1.f / (s1 + expf(sinks[hkv * 8 + h1] - m1));
        __nv_bfloat16* Ph = (__nv_bfloat16*)(smc + BP_H);
        __nv_bfloat16* Pl = (__nv_bfloat16*)(smc + BP_L);
        const int q0 = warp * 8 + h0;
        #pragma unroll
        for (int mt = 0; mt < 9; mt++) {
            #pragma unroll
            for (int k = 0; k < 4; k++) {
                int jj = mt * 16 + jb + (k >> 1) * 8;
                float p = sc[mt][k] * ((k & 1) ? i1 : i0);
                __nv_bfloat16 ph = __float2bfloat16(p);
                __nv_bfloat16 pl = __float2bfloat16(p - __bfloat162float(ph));
                int q = q0 + (k & 1);
                Ph[q * 152 + jj] = ph;
                Pl[q * 152 + jj] = pl;
            }
        }
    }
    __syncthreads();

    {
        const int dt = warp & 3, th = warp >> 2;
        float oc[4][4];
        #pragma unroll
        for (int tt = 0; tt < 4; tt++)
            #pragma unroll
            for (int k = 0; k < 4; k++) oc[tt][k] = 0.f;

        #pragma unroll
        for (int kt = 0; kt < 9; kt++) {
            uint32_t ah[4], al[4];
            uint32_t jrow = (uint32_t)(kt * 16 + (lane & 7) + ((lane >> 4) & 1) * 8);
            uint32_t dcol = (uint32_t)(dt * 16 + ((lane >> 3) & 1) * 8);
            uint32_t va = sb + BV_H + jrow * 144u + dcol * 2u;
            ldsm_x4t(ah, va);
            ldsm_x4t(al, va + (BV_L - BV_H));
            #pragma unroll
            for (int tt = 0; tt < 4; tt++) {
                uint32_t bh[2], bl[2];
                uint32_t pa = sb + BP_H
                            + (uint32_t)((th * 4 + tt) * 8 + (lane & 7)) * 304u
                            + (uint32_t)kt * 32u + (uint32_t)((lane >> 3) & 1) * 16u;
                ldsm_x2(bh, pa);
                ldsm_x2(bl, pa + (BP_L - BP_H));
                mma16816(oc[tt], ah, bh);
                mma16816(oc[tt], al, bh);
                mma16816(oc[tt], ah, bl);
            }
        }
        __syncthreads();
        float* Os = (float*)(smc + BO_F);
        #pragma unroll
        for (int tt = 0; tt < 4; tt++) {
            int q = (th * 4 + tt) * 8 + 2 * (lane & 3);
            int d = dt * 16 + (lane >> 2);
            Os[q * 68 + d]           = oc[tt][0];
            Os[(q + 1) * 68 + d]     = oc[tt][1];
            Os[q * 68 + d + 8]       = oc[tt][2];
            Os[(q + 1) * 68 + d + 8] = oc[tt][3];
        }
    }
    __syncthreads();

    {
        const float* Os = (const float*)(smc + BO_F);
        int q = tid >> 2, d0 = (tid & 3) * 16;
        int tt = t0 + (q >> 3), h = q & 7;
        size_t base = (size_t)tt * QDIM + hkv * 512 + h * HD + d0;
        #pragma unroll
        for (int e = 0; e < 16; e += 4) {
            float f0 = Os[q * 68 + d0 + e];
            float f1 = Os[q * 68 + d0 + e + 1];
            float f2 = Os[q * 68 + d0 + e + 2];
            float f3 = Os[q * 68 + d0 + e + 3];
            uint32_t h0, l0, h1, l1;
            split_pair(f0, f1, h0, l0);
            split_pair(f2, f3, h1, l1);
            *(uint2*)(outh + base + e) = make_uint2(h0, h1);
            *(uint2*)(outl + base + e) = make_uint2(l0, l1);
        }
    }
}

// ---------------------------------------------------------------------------
extern "C" void kernel_launch(void* const* d_in, const int* in_sizes, int n_in,
                              void* d_out, int out_size)
{
    const float* x      = (const float*)d_in[0];
    const float* W_qkv  = (const float*)d_in[1];
    const float* b_qkv  = (const float*)d_in[2];
    const float* W_out  = (const float*)d_in[3];
    const float* b_out  = (const float*)d_in[4];
    const float* sinks  = (const float*)d_in[5];
    float* out = (float*)d_out;

    float *qkv_ptr, *invf_ptr;
    __nv_bfloat16 *xh, *xl, *wqh, *wql, *woh, *wol, *ath, *atl, *qh, *ql;
    cudaGetSymbolAddress((void**)&qkv_ptr, g_qkv);
    cudaGetSymbolAddress((void**)&invf_ptr, g_invf);
    cudaGetSymbolAddress((void**)&xh, g_xh);
    cudaGetSymbolAddress((void**)&xl, g_xl);
    cudaGetSymbolAddress((void**)&wqh, g_wqh);
    cudaGetSymbolAddress((void**)&wql, g_wql);
    cudaGetSymbolAddress((void**)&woh, g_woh);
    cudaGetSymbolAddress((void**)&wol, g_wol);
    cudaGetSymbolAddress((void**)&ath, g_ath);
    cudaGetSymbolAddress((void**)&atl, g_atl);
    cudaGetSymbolAddress((void**)&qh, g_qh);
    cudaGetSymbolAddress((void**)&ql, g_ql);

    cudaFuncSetAttribute(hmma_gemm_bias,
                         cudaFuncAttributeMaxDynamicSharedMemorySize,
                         GEMM_SMEM_BYTES);
    cudaFuncSetAttribute(attn_kernel, cudaFuncAttributeMaxDynamicSharedMemorySize,
                         ATTN_SMEM);

    // 0) rope table + split inputs to bf16 hi/lo
    rope_table_kernel<<<1, 32>>>(invf_ptr);
    {
        int n4 = T_SEQ * D_MODEL / 4;
        split_kernel<<<(n4 + 255) / 256, 256>>>(
            (const float4*)x, (uint2*)xh, (uint2*)xl, n4);
        n4 = D_MODEL * QKV_DIM / 4;
        split_kernel<<<(n4 + 255) / 256, 256>>>(
            (const float4*)W_qkv, (uint2*)wqh, (uint2*)wql, n4);
        n4 = QDIM * D_MODEL / 4;
        split_kernel<<<(n4 + 255) / 256, 256>>>(
            (const float4*)W_out, (uint2*)woh, (uint2*)wol, n4);
    }

    // 1) qkv = x @ W_qkv + b_qkv          (1536 x 5120, K=2880)
    {
        dim3 grid(QKV_DIM / 128, T_SEQ / 128);
        hmma_gemm_bias<<<grid, 256, GEMM_SMEM_BYTES>>>(
            xh, xl, wqh, wql, b_qkv, qkv_ptr, T_SEQ, QKV_DIM, D_MODEL);
    }
    // 2) fused rope + scale + split -> g_qh / g_ql
    rope_split_qkv<<<T_SEQ, 256>>>(qkv_ptr, invf_ptr, qh, ql);

    // 3) 8-token tiled sliding-window GQA attention with sinks
    {
        dim3 grid(T_SEQ / TQ, NKV);
        attn_kernel<<<grid, 256, ATTN_SMEM>>>(qh, ql, sinks, ath, atl);
    }
    // 4) out = attn @ W_out + b_out       (1536 x 2880, K=4096)
    {
        dim3 grid((D_MODEL + 127) / 128, T_SEQ / 128);
        hmma_gemm_bias<<<grid, 256, GEMM_SMEM_BYTES>>>(
            ath, atl, woh, wol, b_out, out, T_SEQ, D_MODEL, QDIM);
    }
}

// round 17
// speedup vs baseline: 1.1417x; 1.1417x over previous
#include <cuda_runtime.h>
#include <cuda_bf16.h>
#include <math.h>
#include <cstdint>

// Problem dims (fixed by reference)
#define T_SEQ   1536
#define D_MODEL 2880
#define NH      64
#define NKV     8
#define HD      64
#define QKV_DIM 5120          // 64*(64+16)
#define QDIM    4096          // NH*HD
#define WIN     128
#define SM_SCALE 0.125f

// Scratch (allocation-free rule: device globals)
__device__ float g_invf[32];                        // rope inv_freq table
// split-bf16 operands
__device__ __nv_bfloat16 g_xh[T_SEQ * D_MODEL];
__device__ __nv_bfloat16 g_xl[T_SEQ * D_MODEL];
__device__ __nv_bfloat16 g_wqh[D_MODEL * QKV_DIM];
__device__ __nv_bfloat16 g_wql[D_MODEL * QKV_DIM];
__device__ __nv_bfloat16 g_woh[QDIM * D_MODEL];
__device__ __nv_bfloat16 g_wol[QDIM * D_MODEL];
__device__ __nv_bfloat16 g_ath[T_SEQ * QDIM];       // attn out hi
__device__ __nv_bfloat16 g_atl[T_SEQ * QDIM];       // attn out lo
__device__ __nv_bfloat16 g_qh[T_SEQ * QKV_DIM];     // roped/scaled qkv hi
__device__ __nv_bfloat16 g_ql[T_SEQ * QKV_DIM];     // roped/scaled qkv lo

// ===========================================================================
// PTX helpers
// ===========================================================================
__device__ __forceinline__ uint32_t smem_u32(const void* p) {
    uint32_t a;
    asm("{ .reg .u64 t; cvta.to.shared.u64 t, %1; cvt.u32.u64 %0, t; }"
        : "=r"(a) : "l"(p));
    return a;
}
__device__ __forceinline__ void ldsm_x4(uint32_t r[4], uint32_t a) {
    asm volatile("ldmatrix.sync.aligned.m8n8.x4.shared.b16 {%0,%1,%2,%3}, [%4];"
        : "=r"(r[0]), "=r"(r[1]), "=r"(r[2]), "=r"(r[3]) : "r"(a));
}
__device__ __forceinline__ void ldsm_x4t(uint32_t r[4], uint32_t a) {
    asm volatile("ldmatrix.sync.aligned.m8n8.x4.trans.shared.b16 {%0,%1,%2,%3}, [%4];"
        : "=r"(r[0]), "=r"(r[1]), "=r"(r[2]), "=r"(r[3]) : "r"(a));
}
__device__ __forceinline__ void ldsm_x2(uint32_t r[2], uint32_t a) {
    asm volatile("ldmatrix.sync.aligned.m8n8.x2.shared.b16 {%0,%1}, [%2];"
        : "=r"(r[0]), "=r"(r[1]) : "r"(a));
}
__device__ __forceinline__ void mma16816(float c[4], const uint32_t a[4],
                                         const uint32_t b[2]) {
    asm volatile(
        "mma.sync.aligned.m16n8k16.row.col.f32.bf16.bf16.f32 "
        "{%0,%1,%2,%3}, {%4,%5,%6,%7}, {%8,%9}, {%0,%1,%2,%3};"
        : "+f"(c[0]), "+f"(c[1]), "+f"(c[2]), "+f"(c[3])
        : "r"(a[0]), "r"(a[1]), "r"(a[2]), "r"(a[3]), "r"(b[0]), "r"(b[1]));
}
__device__ __forceinline__ void cp16(uint32_t saddr, const void* gaddr,
                                     uint32_t srcsize) {
    asm volatile("cp.async.ca.shared.global [%0], [%1], 16, %2;"
        :: "r"(saddr), "l"(gaddr), "r"(srcsize));
}
__device__ __forceinline__ void cp_commit() {
    asm volatile("cp.async.commit_group;" ::: "memory");
}
template <int N>
__device__ __forceinline__ void cp_wait() {
    asm volatile("cp.async.wait_group %0;" :: "n"(N) : "memory");
}
// split fp32 pair into (hi, lo) packed bf16x2
__device__ __forceinline__ void split_pair(float x, float y,
                                           uint32_t& hi, uint32_t& lo) {
    __nv_bfloat16 hx = __float2bfloat16(x);
    __nv_bfloat16 hy = __float2bfloat16(y);
    float rx = x - __bfloat162float(hx);
    float ry = y - __bfloat162float(hy);
    __nv_bfloat162 hp = __halves2bfloat162(hx, hy);
    __nv_bfloat162 lp = __floats2bfloat162_rn(rx, ry);
    hi = *reinterpret_cast<uint32_t*>(&hp);
    lo = *reinterpret_cast<uint32_t*>(&lp);
}

// ===========================================================================
// Split kernel: fp32 -> (hi, lo) bf16, vectorized.
// ===========================================================================
__global__ void __launch_bounds__(256) split_kernel(
    const float4* __restrict__ in, uint2* __restrict__ hi,
    uint2* __restrict__ lo, int n4)
{
    int i = blockIdx.x * 256 + threadIdx.x;
    if (i < n4) {
        float4 v = in[i];
        uint32_t h0, l0, h1, l1;
        split_pair(v.x, v.y, h0, l0);
        split_pair(v.z, v.w, h1, l1);
        hi[i] = make_uint2(h0, h1);
        lo[i] = make_uint2(l0, l1);
    }
}

// ---------------------------------------------------------------------------
// RoPE inv_freq table init (32 threads, double precision, once per launch)
// ---------------------------------------------------------------------------
__global__ void rope_table_kernel(float* __restrict__ invf_out)
{
    const int i = threadIdx.x;   // 0..31
    const double lgbase = log(150000.0);
    const double low  = 32.0 * log(1024.0 / (32.0 * 2.0 * M_PI)) / lgbase;
    const double high = 32.0 * log(1024.0 / ( 1.0 * 2.0 * M_PI)) / lgbase;
    double freq = pow(150000.0, (double)(2 * i) / 64.0);
    double ramp = ((double)i - low) / (high - low);
    ramp = fmin(1.0, fmax(0.0, ramp));
    double invf = ramp / (32.0 * freq) + (1.0 - ramp) / freq;
    invf_out[i] = (float)invf;
}

// ===========================================================================
// Split-bf16 HMMA GEMM with bias (pre-split operands).
// 2-buffer cp.async pipeline, ONE barrier per chunk (race-free ordering:
// prefetch issued AFTER the barrier), 2 CTAs/SM.
// MODE 0: C = fp32 out + bias (GEMM2).
// MODE 1: fused bias + RoPE + SM_SCALE + split-bf16 out (GEMM1 -> qh/ql).
//         Requires N-tiles aligned to Q/K/V regions (4096, 4608 % 128 == 0).
// ===========================================================================
#define SA_HI_OFF 0
#define SA_LO_OFF 10240
#define SB_HI_OFF 20480
#define SB_LO_OFF 29184
#define BUF_STRIDE 37888
#define EP_PITCH  132
#define GEMM_SMEM_BYTES (2 * BUF_STRIDE)   // 75776; 2 CTAs/SM

template <int MODE>
__global__ void __launch_bounds__(256, 2) hmma_gemm_bias(
    const __nv_bfloat16* __restrict__ Ah, const __nv_bfloat16* __restrict__ Al,
    const __nv_bfloat16* __restrict__ Bh, const __nv_bfloat16* __restrict__ Bl,
    const float* __restrict__ bias, float* __restrict__ C,
    const float* __restrict__ invf,
    __nv_bfloat16* __restrict__ Oh, __nv_bfloat16* __restrict__ Ol,
    int M, int N, int K)
{
    extern __shared__ char smem[];
    const uint32_t sb = smem_u32(smem);
    const int tid = threadIdx.x, lane = tid & 31, wid = tid >> 5;
    const int wm = wid >> 2, wn = wid & 3;
    const int m0 = blockIdx.y * 128, n0 = blockIdx.x * 128;

    float acc[4][4][4];
    #pragma unroll
    for (int mi = 0; mi < 4; mi++)
        #pragma unroll
        for (int ni = 0; ni < 4; ni++)
            #pragma unroll
            for (int q = 0; q < 4; q++) acc[mi][ni][q] = 0.f;

    const int am  = tid >> 2;
    const int aks = (tid & 3);
    const int bk  = tid >> 4;
    const int bns = (tid & 15);

    auto issue_chunk = [&](int k0, int buf) {
        const uint32_t bb = sb + (uint32_t)buf * BUF_STRIDE;
        #pragma unroll
        for (int r = 0; r < 2; r++) {
            int m = am + r * 64;
            const __nv_bfloat16* ga = Ah + (size_t)(m0 + m) * K + k0 + aks * 8;
            const __nv_bfloat16* gl = Al + (size_t)(m0 + m) * K + k0 + aks * 8;
            uint32_t so = (uint32_t)m * 80u + (uint32_t)aks * 16u;
            cp16(bb + SA_HI_OFF + so, ga, 16);
            cp16(bb + SA_LO_OFF + so, gl, 16);
        }
        #pragma unroll
        for (int r = 0; r < 2; r++) {
            int k = bk + r * 16;
            int ncol = n0 + bns * 8;
            uint32_t sz = (ncol < N) ? 16u : 0u;
            const __nv_bfloat16* gb = Bh + (size_t)(k0 + k) * N + ncol;
            const __nv_bfloat16* gl = Bl + (size_t)(k0 + k) * N + ncol;
            uint32_t so = (uint32_t)k * 272u + (uint32_t)bns * 16u;
            cp16(bb + SB_HI_OFF + so, gb, sz);
            cp16(bb + SB_LO_OFF + so, gl, sz);
        }
        cp_commit();
    };

    const int nch = K >> 5;
    issue_chunk(0, 0);

    for (int ch = 0; ch < nch; ch++) {
        cp_wait<0>();            // chunk ch landed (issued >= 1 MMA phase ago)
        __syncthreads();         // all warps done reading buffer (ch+1)&1

        // safe: target buffer was last read at chunk ch-1, finished above
        if (ch + 1 < nch) issue_chunk((ch + 1) * 32, (ch + 1) & 1);

        const uint32_t bufb = sb + (uint32_t)(ch & 1) * BUF_STRIDE;
        #pragma unroll
        for (int s = 0; s < 2; s++) {
            uint32_t ah[4][4], al[4][4], bh[4][2], bl[4][2];
            const uint32_t arow  = (uint32_t)(lane & 15);
            const uint32_t acolb = (uint32_t)(s * 32 + (lane >> 4) * 16);
            #pragma unroll
            for (int mi = 0; mi < 4; mi++) {
                uint32_t addr = bufb + SA_HI_OFF
                              + (uint32_t)(wm * 64 + mi * 16 + arow) * 80u + acolb;
                ldsm_x4(ah[mi], addr);
                ldsm_x4(al[mi], addr + (SA_LO_OFF - SA_HI_OFF));
            }
            const uint32_t brow = (uint32_t)(s * 16 + (lane & 15));
            #pragma unroll
            for (int pr = 0; pr < 2; pr++) {
                uint32_t bt[4], btl[4];
                uint32_t addr = bufb + SB_HI_OFF + brow * 272u
                              + (uint32_t)(wn * 32 + pr * 16
                                           + ((lane >> 4) & 1) * 8) * 2u;
                ldsm_x4t(bt, addr);
                ldsm_x4t(btl, addr + (SB_LO_OFF - SB_HI_OFF));
                bh[pr * 2][0]     = bt[0];  bh[pr * 2][1]     = bt[1];
                bh[pr * 2 + 1][0] = bt[2];  bh[pr * 2 + 1][1] = bt[3];
                bl[pr * 2][0]     = btl[0]; bl[pr * 2][1]     = btl[1];
                bl[pr * 2 + 1][0] = btl[2]; bl[pr * 2 + 1][1] = btl[3];
            }
            #pragma unroll
            for (int mi = 0; mi < 4; mi++)
                #pragma unroll
                for (int ni = 0; ni < 4; ni++) {
                    mma16816(acc[mi][ni], ah[mi], bh[ni]);
                    mma16816(acc[mi][ni], al[mi], bh[ni]);
                    mma16816(acc[mi][ni], ah[mi], bl[ni]);
                }
        }
        __syncthreads();
    }

    // ---- epilogue: regs -> smem (pad 132) -> bias (+rope/split) -> out ----
    float* ep = (float*)smem;
    #pragma unroll
    for (int mi = 0; mi < 4; mi++) {
        int r0 = wm * 64 + mi * 16 + (lane >> 2);
        #pragma unroll
        for (int ni = 0; ni < 4; ni++) {
            int c = wn * 32 + ni * 8 + (lane & 3) * 2;
            ep[r0 * EP_PITCH + c]           = acc[mi][ni][0];
            ep[r0 * EP_PITCH + c + 1]       = acc[mi][ni][1];
            ep[(r0 + 8) * EP_PITCH + c]     = acc[mi][ni][2];
            ep[(r0 + 8) * EP_PITCH + c + 1] = acc[mi][ni][3];
        }
    }
    __syncthreads();
    for (int i = tid; i < 4096; i += 256) {
        int r = i >> 5, cq = (i & 31) * 4;
        int col = n0 + cq;
        if (col >= N) continue;
        float4 b4 = *(const float4*)(bias + col);
        float v[4];
        v[0] = ep[r * EP_PITCH + cq + 0] + b4.x;
        v[1] = ep[r * EP_PITCH + cq + 1] + b4.y;
        v[2] = ep[r * EP_PITCH + cq + 2] + b4.z;
        v[3] = ep[r * EP_PITCH + cq + 3] + b4.w;
        if (MODE == 0) {
            float4 o;
            o.x = v[0]; o.y = v[1]; o.z = v[2]; o.w = v[3];
            *(float4*)(C + (size_t)(m0 + r) * N + col) = o;
        } else {
            // fused RoPE (+scale) for Q/K region; V passthrough
            if (col < QDIM + NKV * HD) {
                const int poff = ((col & 63) < 32) ? 32 : -32;
                float4 bp = *(const float4*)(bias + col + poff);
                float p[4];
                p[0] = ep[r * EP_PITCH + cq + poff + 0] + bp.x;
                p[1] = ep[r * EP_PITCH + cq + poff + 1] + bp.y;
                p[2] = ep[r * EP_PITCH + cq + poff + 2] + bp.z;
                p[3] = ep[r * EP_PITCH + cq + poff + 3] + bp.w;
                const float tt = (float)(m0 + r);
                const float conc = 0.1f * logf(32.0f) + 1.0f;
                const float scale = (col < QDIM) ? SM_SCALE : 1.0f;
                #pragma unroll
                for (int e = 0; e < 4; e++) {
                    float ang = tt * __ldg(&invf[(col + e) & 31]);
                    float s, c;
                    sincosf(ang, &s, &c);
                    c *= conc; s *= conc;
                    float rv = (poff == 32) ? (v[e] * c - p[e] * s)
                                            : (v[e] * c + p[e] * s);
                    v[e] = rv * scale;
                }
            }
            uint32_t h0, l0, h1, l1;
            split_pair(v[0], v[1], h0, l0);
            split_pair(v[2], v[3], h1, l1);
            size_t o = (size_t)(m0 + r) * N + col;
            *(uint2*)(Oh + o) = make_uint2(h0, h1);
            *(uint2*)(Ol + o) = make_uint2(l0, l1);
        }
    }
}

// ===========================================================================
// 8-token tiled MMA attention: block = (8 tokens, kv head), 256 threads.
// ===========================================================================
#define TQ   8
#define JT   144
#define BK_H 0
#define BK_L 20736
#define BV_H 41472
#define BV_L 62208
#define BQ_H 82944
#define BQ_L 92160
#define BP_H 101376
#define BP_L 120832
#define BO_F BQ_H                    // fp32 [64 q][68 d] aliases Q (17408<=18432)
#define ATTN_SMEM 140288

__global__ void __launch_bounds__(256) attn_kernel(
    const __nv_bfloat16* __restrict__ qh, const __nv_bfloat16* __restrict__ ql,
    const float* __restrict__ sinks,
    __nv_bfloat16* __restrict__ outh, __nv_bfloat16* __restrict__ outl)
{
    extern __shared__ char smc[];
    const uint32_t sb = smem_u32(smc);
    const int t0  = blockIdx.x * TQ;
    const int hkv = blockIdx.y;
    const int j0  = max(0, t0 - (WIN - 1));
    const int cntrows = t0 + TQ - j0;          // <= 135
    const int tid = threadIdx.x;
    const int warp = tid >> 5;
    const int lane = tid & 31;

    for (int i = tid; i < JT * 8; i += 256) {
        int jj = i >> 3, c8 = i & 7;
        int jc = min(jj, cntrows - 1);
        uint32_t sz = (jj < cntrows) ? 16u : 0u;
        size_t srck = (size_t)(j0 + jc) * QKV_DIM + QDIM + hkv * HD + c8 * 8;
        size_t srcv = srck + NKV * HD;
        uint32_t off = (uint32_t)jj * 144u + (uint32_t)c8 * 16u;
        cp16(sb + BK_H + off, qh + srck, sz);
        cp16(sb + BK_L + off, ql + srck, sz);
        cp16(sb + BV_H + off, qh + srcv, sz);
        cp16(sb + BV_L + off, ql + srcv, sz);
    }
    for (int i = tid; i < 1024; i += 256) {
        int hilo = i >> 9, row = (i >> 3) & 63, c8 = i & 7;
        int tt = t0 + (row >> 3), head = row & 7;
        size_t src = (size_t)tt * QKV_DIM + (hkv * 8 + head) * HD + c8 * 8;
        uint32_t off = (uint32_t)row * 144u + (uint32_t)c8 * 16u;
        if (hilo == 0) cp16(sb + BQ_H + off, qh + src, 16);
        else           cp16(sb + BQ_L + off, ql + src, 16);
    }
    cp_commit();
    cp_wait<0>();
    __syncthreads();

    const int tw  = t0 + warp;
    const int jlo = max(0, tw - (WIN - 1) - j0);
    const int jhi = tw - j0;

    float sc[9][4];
    {
        uint32_t bh[4][2], bl[4][2];
        #pragma unroll
        for (int ks = 0; ks < 4; ks++) {
            uint32_t addr = sb + BQ_H
                          + (uint32_t)(warp * 8 + (lane & 7)) * 144u
                          + (uint32_t)ks * 32u + (uint32_t)((lane >> 3) & 1) * 16u;
            ldsm_x2(bh[ks], addr);
            ldsm_x2(bl[ks], addr + (BQ_L - BQ_H));
        }
        #pragma unroll
        for (int mt = 0; mt < 9; mt++) {
            float c[4] = {0.f, 0.f, 0.f, 0.f};
            #pragma unroll
            for (int ks = 0; ks < 4; ks++) {
                uint32_t ah[4], al[4];
                uint32_t addr = sb + BK_H
                              + (uint32_t)(mt * 16 + (lane & 15)) * 144u
                              + (uint32_t)ks * 32u + (uint32_t)(lane >> 4) * 16u;
                ldsm_x4(ah, addr);
                ldsm_x4(al, addr + (BK_L - BK_H));
                mma16816(c, ah, bh[ks]);
                mma16816(c, al, bh[ks]);
                mma16816(c, ah, bl[ks]);
            }
            sc[mt][0] = c[0]; sc[mt][1] = c[1]; sc[mt][2] = c[2]; sc[mt][3] = c[3];
        }
    }

    {
        const int jb = lane >> 2;
        float m0 = -INFINITY, m1 = -INFINITY;
        #pragma unroll
        for (int mt = 0; mt < 9; mt++) {
            #pragma unroll
            for (int k = 0; k < 4; k++) {
                int jj = mt * 16 + jb + (k >> 1) * 8;
                if (jj < jlo || jj > jhi) sc[mt][k] = -INFINITY;
                if (k & 1) m1 = fmaxf(m1, sc[mt][k]);
                else       m0 = fmaxf(m0, sc[mt][k]);
            }
        }
        #pragma unroll
        for (int o = 4; o <= 16; o <<= 1) {
            m0 = fmaxf(m0, __shfl_xor_sync(~0u, m0, o));
            m1 = fmaxf(m1, __shfl_xor_sync(~0u, m1, o));
        }
        float s0 = 0.f, s1 = 0.f;
        #pragma unroll
        for (int mt = 0; mt < 9; mt++) {
            #pragma unroll
            for (int k = 0; k < 4; k++) {
                float m = (k & 1) ? m1 : m0;
                float e = (sc[mt][k] == -INFINITY) ? 0.f : expf(sc[mt][k] - m);
                sc[mt][k] = e;
                if (k & 1) s1 += e; else s0 += e;
            }
        }
        #pragma unroll
        for (int o = 4; o <= 16; o <<= 1) {
            s0 += __shfl_xor_sync(~0u, s0, o);
            s1 += __shfl_xor_sync(~0u, s1, o);
        }
        const int h0 = 2 * (lane & 3), h1 = h0 + 1;
        const float i0 = 1.f / (s0 + expf(sinks[hkv * 8 + h0] - m0));
        const float i1 = 1.f / (s1 + expf(sinks[hkv * 8 + h1] - m1));
        __nv_bfloat16* Ph = (__nv_bfloat16*)(smc + BP_H);
        __nv_bfloat16* Pl = (__nv_bfloat16*)(smc + BP_L);
        const int q0 = warp * 8 + h0;
        #pragma unroll
        for (int mt = 0; mt < 9; mt++) {
            #pragma unroll
            for (int k = 0; k < 4; k++) {
                int jj = mt * 16 + jb + (k >> 1) * 8;
                float p = sc[mt][k] * ((k & 1) ? i1 : i0);
                __nv_bfloat16 ph = __float2bfloat16(p);
                __nv_bfloat16 pl = __float2bfloat16(p - __bfloat162float(ph));
                int q = q0 + (k & 1);
                Ph[q * 152 + jj] = ph;
                Pl[q * 152 + jj] = pl;
            }
        }
    }
    __syncthreads();

    {
        const int dt = warp & 3, th = warp >> 2;
        float oc[4][4];
        #pragma unroll
        for (int tt = 0; tt < 4; tt++)
            #pragma unroll
            for (int k = 0; k < 4; k++) oc[tt][k] = 0.f;

        #pragma unroll
        for (int kt = 0; kt < 9; kt++) {
            uint32_t ah[4], al[4];
            uint32_t jrow = (uint32_t)(kt * 16 + (lane & 7) + ((lane >> 4) & 1) * 8);
            uint32_t dcol = (uint32_t)(dt * 16 + ((lane >> 3) & 1) * 8);
            uint32_t va = sb + BV_H + jrow * 144u + dcol * 2u;
            ldsm_x4t(ah, va);
            ldsm_x4t(al, va + (BV_L - BV_H));
            #pragma unroll
            for (int tt = 0; tt < 4; tt++) {
                uint32_t bh[2], bl[2];
                uint32_t pa = sb + BP_H
                            + (uint32_t)((th * 4 + tt) * 8 + (lane & 7)) * 304u
                            + (uint32_t)kt * 32u + (uint32_t)((lane >> 3) & 1) * 16u;
                ldsm_x2(bh, pa);
                ldsm_x2(bl, pa + (BP_L - BP_H));
                mma16816(oc[tt], ah, bh);
                mma16816(oc[tt], al, bh);
                mma16816(oc[tt], ah, bl);
            }
        }
        __syncthreads();
        float* Os = (float*)(smc + BO_F);
        #pragma unroll
        for (int tt = 0; tt < 4; tt++) {
            int q = (th * 4 + tt) * 8 + 2 * (lane & 3);
            int d = dt * 16 + (lane >> 2);
            Os[q * 68 + d]           = oc[tt][0];
            Os[(q + 1) * 68 + d]     = oc[tt][1];
            Os[q * 68 + d + 8]       = oc[tt][2];
            Os[(q + 1) * 68 + d + 8] = oc[tt][3];
        }
    }
    __syncthreads();

    {
        const float* Os = (const float*)(smc + BO_F);
        int q = tid >> 2, d0 = (tid & 3) * 16;
        int tt = t0 + (q >> 3), h = q & 7;
        size_t base = (size_t)tt * QDIM + hkv * 512 + h * HD + d0;
        #pragma unroll
        for (int e = 0; e < 16; e += 4) {
            float f0 = Os[q * 68 + d0 + e];
            float f1 = Os[q * 68 + d0 + e + 1];
            float f2 = Os[q * 68 + d0 + e + 2];
            float f3 = Os[q * 68 + d0 + e + 3];
            uint32_t h0, l0, h1, l1;
            split_pair(f0, f1, h0, l0);
            split_pair(f2, f3, h1, l1);
            *(uint2*)(outh + base + e) = make_uint2(h0, h1);
            *(uint2*)(outl + base + e) = make_uint2(l0, l1);
        }
    }
}

// ---------------------------------------------------------------------------
extern "C" void kernel_launch(void* const* d_in, const int* in_sizes, int n_in,
                              void* d_out, int out_size)
{
    const float* x      = (const float*)d_in[0];
    const float* W_qkv  = (const float*)d_in[1];
    const float* b_qkv  = (const float*)d_in[2];
    const float* W_out  = (const float*)d_in[3];
    const float* b_out  = (const float*)d_in[4];
    const float* sinks  = (const float*)d_in[5];
    float* out = (float*)d_out;

    float *invf_ptr;
    __nv_bfloat16 *xh, *xl, *wqh, *wql, *woh, *wol, *ath, *atl, *qh, *ql;
    cudaGetSymbolAddress((void**)&invf_ptr, g_invf);
    cudaGetSymbolAddress((void**)&xh, g_xh);
    cudaGetSymbolAddress((void**)&xl, g_xl);
    cudaGetSymbolAddress((void**)&wqh, g_wqh);
    cudaGetSymbolAddress((void**)&wql, g_wql);
    cudaGetSymbolAddress((void**)&woh, g_woh);
    cudaGetSymbolAddress((void**)&wol, g_wol);
    cudaGetSymbolAddress((void**)&ath, g_ath);
    cudaGetSymbolAddress((void**)&atl, g_atl);
    cudaGetSymbolAddress((void**)&qh, g_qh);
    cudaGetSymbolAddress((void**)&ql, g_ql);

    cudaFuncSetAttribute(hmma_gemm_bias<0>,
                         cudaFuncAttributeMaxDynamicSharedMemorySize,
                         GEMM_SMEM_BYTES);
    cudaFuncSetAttribute(hmma_gemm_bias<1>,
                         cudaFuncAttributeMaxDynamicSharedMemorySize,
                         GEMM_SMEM_BYTES);
    cudaFuncSetAttribute(attn_kernel, cudaFuncAttributeMaxDynamicSharedMemorySize,
                         ATTN_SMEM);

    // 0) rope table + split inputs to bf16 hi/lo
    rope_table_kernel<<<1, 32>>>(invf_ptr);
    {
        int n4 = T_SEQ * D_MODEL / 4;
        split_kernel<<<(n4 + 255) / 256, 256>>>(
            (const float4*)x, (uint2*)xh, (uint2*)xl, n4);
        n4 = D_MODEL * QKV_DIM / 4;
        split_kernel<<<(n4 + 255) / 256, 256>>>(
            (const float4*)W_qkv, (uint2*)wqh, (uint2*)wql, n4);
        n4 = QDIM * D_MODEL / 4;
        split_kernel<<<(n4 + 255) / 256, 256>>>(
            (const float4*)W_out, (uint2*)woh, (uint2*)wol, n4);
    }

    // 1) qkv = x @ W_qkv + b_qkv, fused RoPE+scale+split -> g_qh/g_ql
    {
        dim3 grid(QKV_DIM / 128, T_SEQ / 128);
        hmma_gemm_bias<1><<<grid, 256, GEMM_SMEM_BYTES>>>(
            xh, xl, wqh, wql, b_qkv, nullptr, invf_ptr, qh, ql,
            T_SEQ, QKV_DIM, D_MODEL);
    }
    // 2) 8-token tiled sliding-window GQA attention with sinks
    {
        dim3 grid(T_SEQ / TQ, NKV);
        attn_kernel<<<grid, 256, ATTN_SMEM>>>(qh, ql, sinks, ath, atl);
    }
    // 3) out = attn @ W_out + b_out       (1536 x 2880, K=4096)
    {
        dim3 grid((D_MODEL + 127) / 128, T_SEQ / 128);
        hmma_gemm_bias<0><<<grid, 256, GEMM_SMEM_BYTES>>>(
            ath, atl, woh, wol, b_out, out, nullptr, nullptr, nullptr,
            T_SEQ, D_MODEL, QDIM);
    }
}